// round 11
// baseline (speedup 1.0000x reference)
#include <cuda_runtime.h>
#include <cuda_bf16.h>
#include <stdint.h>
#include <math.h>

#define TOK   8192
#define DM    1024
#define DQKV  3072
#define DFF   2048
#define SEQ   2048

// ---------------- scratch planes (device globals: allocation-free) ----------------
__device__ __nv_bfloat16 g_h1h[TOK*DM],   g_h1l[TOK*DM];     // LN1 out
__device__ __nv_bfloat16 g_qkh[TOK*DQKV], g_qkl[TOK*DQKV];   // qkv (Q pre-scaled)
__device__ __nv_bfloat16 g_cxh[TOK*DM],   g_cxl[TOK*DM];     // attn ctx
__device__ __nv_bfloat16 g_h2h[TOK*DM],   g_h2l[TOK*DM];     // LN2 out
__device__ __nv_bfloat16 g_ffh[TOK*DFF],  g_ffl[TOK*DFF];    // ff1 out (post-GELU)
__device__ float         g_x1 [TOK*DM];                      // residual1 fp32
__device__ __nv_bfloat16 g_wqh[DM*DQKV],  g_wql[DM*DQKV];
__device__ __nv_bfloat16 g_woh[DM*DM],    g_wol[DM*DM];
__device__ __nv_bfloat16 g_w1h[DM*DFF],   g_w1l[DM*DFF];
__device__ __nv_bfloat16 g_w2h[DFF*DM],   g_w2l[DFF*DM];

// ---------------- helpers ----------------
__device__ __forceinline__ unsigned pk2(float lo, float hi) {   // lo -> bits[15:0]
    unsigned d;
    asm("cvt.rn.bf16x2.f32 %0, %1, %2;" : "=r"(d) : "f"(hi), "f"(lo));
    return d;
}
__device__ __forceinline__ void split_store(__nv_bfloat16* H, __nv_bfloat16* L,
                                            size_t off, float x0, float x1) {
    float h0 = __bfloat162float(__float2bfloat16(x0));
    float h1 = __bfloat162float(__float2bfloat16(x1));
    *(unsigned*)((char*)H + off*2) = pk2(h0, h1);
    *(unsigned*)((char*)L + off*2) = pk2(x0 - h0, x1 - h1);
}
__device__ __forceinline__ void split_pk(float x0, float x1, unsigned& hp, unsigned& lp) {
    float h0 = __bfloat162float(__float2bfloat16(x0));
    float h1 = __bfloat162float(__float2bfloat16(x1));
    hp = pk2(h0, h1);
    lp = pk2(x0 - h0, x1 - h1);
}
__device__ __forceinline__ void ldsm4(unsigned& r0, unsigned& r1, unsigned& r2, unsigned& r3, unsigned a) {
    asm volatile("ldmatrix.sync.aligned.m8n8.x4.shared.b16 {%0,%1,%2,%3}, [%4];"
                 : "=r"(r0), "=r"(r1), "=r"(r2), "=r"(r3) : "r"(a));
}
__device__ __forceinline__ void ldsm2(unsigned& r0, unsigned& r1, unsigned a) {
    asm volatile("ldmatrix.sync.aligned.m8n8.x2.shared.b16 {%0,%1}, [%2];"
                 : "=r"(r0), "=r"(r1) : "r"(a));
}
__device__ __forceinline__ void ldsm2t(unsigned& r0, unsigned& r1, unsigned a) {
    asm volatile("ldmatrix.sync.aligned.m8n8.x2.trans.shared.b16 {%0,%1}, [%2];"
                 : "=r"(r0), "=r"(r1) : "r"(a));
}
// NOTE: non-volatile — pure register function, lets ptxas schedule/interleave
__device__ __forceinline__ void mma16816(float* c, const unsigned* a, const unsigned* b) {
    asm("mma.sync.aligned.m16n8k16.row.col.f32.bf16.bf16.f32 "
        "{%0,%1,%2,%3},{%4,%5,%6,%7},{%8,%9},{%0,%1,%2,%3};"
        : "+f"(c[0]), "+f"(c[1]), "+f"(c[2]), "+f"(c[3])
        : "r"(a[0]), "r"(a[1]), "r"(a[2]), "r"(a[3]), "r"(b[0]), "r"(b[1]));
}
#define CPA(dst, src) asm volatile("cp.async.cg.shared.global [%0], [%1], 16;" ::"r"(dst), "l"(src))
#define CPC()         asm volatile("cp.async.commit_group;")
#define CPW(n)        asm volatile("cp.async.wait_group %0;" ::"n"(n))

// ---------------- weight split (no transpose needed for mma.sync path) ----------------
__global__ void wconv(const float* __restrict__ W, __nv_bfloat16* __restrict__ H,
                      __nv_bfloat16* __restrict__ L, int n4) {
    int i = blockIdx.x * 256 + threadIdx.x;
    if (i >= n4) return;
    float4 v = ((const float4*)W)[i];
    split_store(H, L, (size_t)i * 4,     v.x, v.y);
    split_store(H, L, (size_t)i * 4 + 2, v.z, v.w);
}

// ---------------- LayerNorm -> hi/lo planes ----------------
__global__ void ln_kernel(const float* __restrict__ x, const float* __restrict__ gam,
                          const float* __restrict__ bet,
                          __nv_bfloat16* __restrict__ H, __nv_bfloat16* __restrict__ L) {
    const int row = blockIdx.x;
    const int t   = threadIdx.x;
    const float* xr = x + (size_t)row * DM;
    const int c0 = t * 4;
    float4 v = *(const float4*)(xr + c0);
    float s  = v.x + v.y + v.z + v.w;
    float ss = v.x*v.x + v.y*v.y + v.z*v.z + v.w*v.w;
    #pragma unroll
    for (int o = 16; o; o >>= 1) {
        s  += __shfl_xor_sync(0xffffffffu, s,  o);
        ss += __shfl_xor_sync(0xffffffffu, ss, o);
    }
    __shared__ float sm[8], sm2[8];
    const int w = t >> 5;
    if ((t & 31) == 0) { sm[w] = s; sm2[w] = ss; }
    __syncthreads();
    if (w == 0) {
        float a = (t < 8) ? sm[t] : 0.f;
        float c = (t < 8) ? sm2[t] : 0.f;
        #pragma unroll
        for (int o = 4; o; o >>= 1) {
            a += __shfl_xor_sync(0xffffffffu, a, o);
            c += __shfl_xor_sync(0xffffffffu, c, o);
        }
        if (t == 0) {
            float mu = a * (1.0f / DM);
            float var = c * (1.0f / DM) - mu * mu;
            sm[0] = mu; sm2[0] = rsqrtf(var + 1e-5f);
        }
    }
    __syncthreads();
    const float mu = sm[0], rs = sm2[0];
    float4 g4 = *(const float4*)(gam + c0);
    float4 b4 = *(const float4*)(bet + c0);
    float o0 = (v.x - mu) * rs * g4.x + b4.x;
    float o1 = (v.y - mu) * rs * g4.y + b4.y;
    float o2 = (v.z - mu) * rs * g4.z + b4.z;
    float o3 = (v.w - mu) * rs * g4.w + b4.w;
    size_t off = (size_t)row * DM + c0;
    split_store(H, L, off,     o0, o1);
    split_store(H, L, off + 2, o2, o3);
}

// ---------------- split-bf16 tensor-core GEMM (mma.sync, dependency-spread) ----------------
// C[M,N] = A[M,K] @ B[K,N] (+bias...). A,B given as hi/lo bf16 planes.
// 128x128 block, BK=16, 3-stage cp.async. 8 warps = 2(m) x 4(n); warptile 64x32.
// EPI: 0 = bias (+0.125 scale on cols<1024) -> planes; 1 = bias+res -> fp32; 2 = bias+GELU -> planes
template<int EPI>
__global__ __launch_bounds__(256, 2)
void mgemm(const __nv_bfloat16* __restrict__ Ah, const __nv_bfloat16* __restrict__ Al,
           const __nv_bfloat16* __restrict__ Bh, const __nv_bfloat16* __restrict__ Bl,
           const float* __restrict__ bias, const float* __restrict__ res,
           float* __restrict__ outF, __nv_bfloat16* __restrict__ outH, __nv_bfloat16* __restrict__ outL,
           int M, int N, int K) {
    // stage layout (16KB): A[0,8K): row m/2 (128B = m-even|m-odd, each 16k x 2 planes),
    //                      Bh[8K,12K), Bl[12K,16K): row k (256B = 128 n)
    __shared__ char smem[49152];
    const unsigned sbase = (unsigned)__cvta_generic_to_shared(smem);
    const int tid = threadIdx.x;
    const int rb = blockIdx.y << 7, cb = blockIdx.x << 7;

    const __nv_bfloat16* aS[2]; unsigned aD[2];
    const __nv_bfloat16* bS[2]; unsigned bD[2];
    #pragma unroll
    for (int j = 0; j < 2; j++) {
        int ca = tid + j * 256;
        int m = ca & 127, f = ca >> 7;
        int p = f >> 1, kc = f & 1;
        aS[j] = (p ? Al : Ah) + (size_t)(rb + m) * K + kc * 8;
        aD[j] = (m >> 1) * 128 + ((((m & 1) * 4) + p * 2 + kc) ^ ((m >> 1) & 7)) * 16;
        int nc = ca & 15, k = (ca >> 4) & 15, p2 = ca >> 8;
        bS[j] = (p2 ? Bl : Bh) + (size_t)k * N + cb + nc * 8;
        bD[j] = 8192 + p2 * 4096 + k * 256 + ((nc ^ (k & 7)) * 16);
    }
    const int nk = K >> 4;

    #define G_ISSUE(st, i) do { unsigned _b = sbase + (st) * 16384;                      \
        CPA(_b + aD[0], aS[0] + (i) * 16);  CPA(_b + aD[1], aS[1] + (i) * 16);           \
        CPA(_b + bD[0], bS[0] + (size_t)(i) * 16 * N);                                   \
        CPA(_b + bD[1], bS[1] + (size_t)(i) * 16 * N);  CPC(); } while (0)

    G_ISSUE(0, 0);
    G_ISSUE(1, 1);

    const int wid = tid >> 5, lane = tid & 31;
    const int wm = (wid >> 2) * 64, wn = (wid & 3) * 32;
    const int arl = (lane & 7) + 8 * ((lane >> 3) & 1);
    const int akc = (lane >> 4) & 1;
    const int brow = lane & 15;

    float acc[4][4][4];
    #pragma unroll
    for (int a = 0; a < 4; a++)
        #pragma unroll
        for (int b = 0; b < 4; b++)
            #pragma unroll
            for (int e = 0; e < 4; e++) acc[a][b][e] = 0.f;

    for (int i = 0; i < nk; i++) {
        if (i == nk - 1) { CPW(0); } else { CPW(1); }
        __syncthreads();
        if (i + 2 < nk) {
            int st = (i + 2) % 3;
            G_ISSUE(st, i + 2);
        }
        const unsigned stb = sbase + (i % 3) * 16384;

        unsigned bh[4][2], bl[4][2];
        #pragma unroll
        for (int nt = 0; nt < 4; nt++) {
            int nc = (wn + nt * 8) >> 3;
            unsigned ad = stb + 8192 + brow * 256 + ((nc ^ (brow & 7)) * 16);
            ldsm2t(bh[nt][0], bh[nt][1], ad);
            ldsm2t(bl[nt][0], bl[nt][1], ad + 4096);
        }
        #pragma unroll
        for (int mt = 0; mt < 4; mt++) {
            int m = wm + mt * 16 + arl;
            unsigned base = stb + (m >> 1) * 128;
            unsigned Af[4], Lf[4];
            ldsm4(Af[0], Af[1], Af[2], Af[3], base + ((((m & 1) * 4) + akc)     ^ ((m >> 1) & 7)) * 16);
            ldsm4(Lf[0], Lf[1], Lf[2], Lf[3], base + ((((m & 1) * 4) + 2 + akc) ^ ((m >> 1) & 7)) * 16);
            // term-outer: same-acc mma reuse distance = 4 (was 1 -> RAW serialization)
            #pragma unroll
            for (int nt = 0; nt < 4; nt++) mma16816(acc[mt][nt], Af, bh[nt]);
            #pragma unroll
            for (int nt = 0; nt < 4; nt++) mma16816(acc[mt][nt], Af, bl[nt]);
            #pragma unroll
            for (int nt = 0; nt < 4; nt++) mma16816(acc[mt][nt], Lf, bh[nt]);
        }
        __syncthreads();
    }

    const float qs = (EPI == 0 && cb < 1024) ? 0.125f : 1.0f;
    #pragma unroll
    for (int mt = 0; mt < 4; mt++) {
        #pragma unroll
        for (int nt = 0; nt < 4; nt++) {
            int gr0 = rb + wm + mt * 16 + (lane >> 2);
            int gc  = cb + wn + nt * 8 + (lane & 3) * 2;
            float b0 = bias[gc], b1 = bias[gc + 1];
            #pragma unroll
            for (int hf = 0; hf < 2; hf++) {
                int gr = gr0 + hf * 8;
                float v0 = acc[mt][nt][hf * 2 + 0] + b0;
                float v1 = acc[mt][nt][hf * 2 + 1] + b1;
                size_t off = (size_t)gr * N + gc;
                if (EPI == 0) {
                    split_store(outH, outL, off, v0 * qs, v1 * qs);
                } else if (EPI == 1) {
                    v0 += res[off]; v1 += res[off + 1];
                    outF[off] = v0; outF[off + 1] = v1;
                } else {
                    v0 = 0.5f * v0 * (1.0f + erff(v0 * 0.70710678118654752f));
                    v1 = 0.5f * v1 * (1.0f + erff(v1 * 0.70710678118654752f));
                    split_store(outH, outL, off, v0, v1);
                }
            }
        }
    }
    #undef G_ISSUE
}

// ---------------- tensor-core flash attention (dependency-spread) ----------------
__global__ __launch_bounds__(128, 3)
void attn_kernel(const __nv_bfloat16* __restrict__ Ph, const __nv_bfloat16* __restrict__ Pl,
                 __nv_bfloat16* __restrict__ Oh, __nv_bfloat16* __restrict__ Ol) {
    __shared__ char smem[49152];
    const unsigned sbase = (unsigned)__cvta_generic_to_shared(smem);
    const int b = blockIdx.z, hh = blockIdx.y, q0 = blockIdx.x * 64;
    const int tid = threadIdx.x, wid = tid >> 5, lane = tid & 31;

    #pragma unroll
    for (int j = 0; j < 8; j++) {
        int qc = tid + j * 128;
        int row = qc & 63, rest = qc >> 6;
        int dc = rest & 7, p = rest >> 3;
        const __nv_bfloat16* src = (p ? Pl : Ph) + (size_t)(b * SEQ + q0 + row) * DQKV + hh * 64 + dc * 8;
        *(uint4*)(smem + row * 256 + (((dc ^ (row & 7)) + p * 8) * 16)) = *(const uint4*)src;
    }
    __syncthreads();

    const int arl = (lane & 7) + 8 * ((lane >> 3) & 1);
    const int akc = (lane >> 4) & 1;
    unsigned qf[4][2][4];
    #pragma unroll
    for (int kc = 0; kc < 4; kc++)
        #pragma unroll
        for (int p = 0; p < 2; p++) {
            int row = wid * 16 + arl;
            int dc = kc * 2 + akc;
            unsigned ad = sbase + row * 256 + (((dc ^ (row & 7)) + p * 8) * 16);
            ldsm4(qf[kc][p][0], qf[kc][p][1], qf[kc][p][2], qf[kc][p][3], ad);
        }

    const __nv_bfloat16* kvS[8]; unsigned kvD[8];
    #pragma unroll
    for (int j = 0; j < 8; j++) {
        int cc = tid + j * 128;
        int dc = cc & 7, key = (cc >> 3) & 31, rest = cc >> 8;
        int p = rest & 1, mat = rest >> 1;
        kvS[j] = (p ? Pl : Ph) + (size_t)(b * SEQ + key) * DQKV + 1024 + mat * 1024 + hh * 64 + dc * 8;
        kvD[j] = (mat * 2 + p) * 4096 + key * 128 + ((dc ^ (key & 7)) * 16);
    }
    #define A_ISSUE(t) do { unsigned _b = sbase + 16384 + ((t) & 1) * 16384;             \
        _Pragma("unroll") for (int j = 0; j < 8; j++)                                    \
            CPA(_b + kvD[j], kvS[j] + (size_t)(t) * 32 * DQKV);                          \
        CPC(); } while (0)

    A_ISSUE(0);

    float o[8][4];
    #pragma unroll
    for (int i = 0; i < 8; i++)
        #pragma unroll
        for (int e = 0; e < 4; e++) o[i][e] = 0.f;
    float m0 = -1e30f, m1 = -1e30f, l0 = 0.f, l1 = 0.f;

    for (int t = 0; t < SEQ / 32; t++) {
        if (t + 1 < SEQ / 32) { A_ISSUE(t + 1); CPW(1); } else { CPW(0); }
        __syncthreads();
        const unsigned stb = sbase + 16384 + (t & 1) * 16384;

        // S = Q K^T (16x32 per warp): per kc, load all K frags, term-outer mma (distance 4)
        float s[4][4];
        #pragma unroll
        for (int nt = 0; nt < 4; nt++)
            #pragma unroll
            for (int e = 0; e < 4; e++) s[nt][e] = 0.f;
        {
            int row = (lane & 7);
            int kch = ((lane >> 3) & 1);
            #pragma unroll
            for (int kc = 0; kc < 4; kc++) {
                unsigned kh[4][2], kl[4][2];
                #pragma unroll
                for (int nt = 0; nt < 4; nt++) {
                    int r = nt * 8 + row;
                    int chunk = kc * 2 + kch;
                    unsigned kd = stb + r * 128 + ((chunk ^ (r & 7)) * 16);
                    ldsm2(kh[nt][0], kh[nt][1], kd);
                    ldsm2(kl[nt][0], kl[nt][1], kd + 4096);
                }
                #pragma unroll
                for (int nt = 0; nt < 4; nt++) mma16816(s[nt], qf[kc][0], kh[nt]);
                #pragma unroll
                for (int nt = 0; nt < 4; nt++) mma16816(s[nt], qf[kc][0], kl[nt]);
                #pragma unroll
                for (int nt = 0; nt < 4; nt++) mma16816(s[nt], qf[kc][1], kh[nt]);
            }
        }
        float mx0 = -1e30f, mx1 = -1e30f;
        #pragma unroll
        for (int nt = 0; nt < 4; nt++) {
            mx0 = fmaxf(mx0, fmaxf(s[nt][0], s[nt][1]));
            mx1 = fmaxf(mx1, fmaxf(s[nt][2], s[nt][3]));
        }
        mx0 = fmaxf(mx0, __shfl_xor_sync(0xffffffffu, mx0, 1));
        mx0 = fmaxf(mx0, __shfl_xor_sync(0xffffffffu, mx0, 2));
        mx1 = fmaxf(mx1, __shfl_xor_sync(0xffffffffu, mx1, 1));
        mx1 = fmaxf(mx1, __shfl_xor_sync(0xffffffffu, mx1, 2));
        float mn0 = fmaxf(m0, mx0), mn1 = fmaxf(m1, mx1);
        float c0 = __expf(m0 - mn0), c1 = __expf(m1 - mn1);
        m0 = mn0; m1 = mn1;
        l0 *= c0; l1 *= c1;
        #pragma unroll
        for (int nt = 0; nt < 4; nt++) {
            s[nt][0] = __expf(s[nt][0] - m0); l0 += s[nt][0];
            s[nt][1] = __expf(s[nt][1] - m0); l0 += s[nt][1];
            s[nt][2] = __expf(s[nt][2] - m1); l1 += s[nt][2];
            s[nt][3] = __expf(s[nt][3] - m1); l1 += s[nt][3];
        }
        #pragma unroll
        for (int nt = 0; nt < 8; nt++) {
            o[nt][0] *= c0; o[nt][1] *= c0; o[nt][2] *= c1; o[nt][3] *= c1;
        }
        unsigned ph[2][4], pl[2][4];
        #pragma unroll
        for (int kc2 = 0; kc2 < 2; kc2++) {
            split_pk(s[2 * kc2][0],     s[2 * kc2][1],     ph[kc2][0], pl[kc2][0]);
            split_pk(s[2 * kc2][2],     s[2 * kc2][3],     ph[kc2][1], pl[kc2][1]);
            split_pk(s[2 * kc2 + 1][0], s[2 * kc2 + 1][1], ph[kc2][2], pl[kc2][2]);
            split_pk(s[2 * kc2 + 1][2], s[2 * kc2 + 1][3], ph[kc2][3], pl[kc2][3]);
        }
        // O += P V: per kc2, load all V frags, term-outer mma (distance 8)
        #pragma unroll
        for (int kc2 = 0; kc2 < 2; kc2++) {
            int row = kc2 * 16 + (lane & 15);
            unsigned vh[8][2], vl[8][2];
            #pragma unroll
            for (int nt = 0; nt < 8; nt++) {
                unsigned vd = stb + 8192 + row * 128 + ((nt ^ (row & 7)) * 16);
                ldsm2t(vh[nt][0], vh[nt][1], vd);
                ldsm2t(vl[nt][0], vl[nt][1], vd + 4096);
            }
            #pragma unroll
            for (int nt = 0; nt < 8; nt++) mma16816(o[nt], ph[kc2], vh[nt]);
            #pragma unroll
            for (int nt = 0; nt < 8; nt++) mma16816(o[nt], ph[kc2], vl[nt]);
            #pragma unroll
            for (int nt = 0; nt < 8; nt++) mma16816(o[nt], pl[kc2], vh[nt]);
        }
        __syncthreads();
    }

    l0 += __shfl_xor_sync(0xffffffffu, l0, 1);
    l0 += __shfl_xor_sync(0xffffffffu, l0, 2);
    l1 += __shfl_xor_sync(0xffffffffu, l1, 1);
    l1 += __shfl_xor_sync(0xffffffffu, l1, 2);
    const float i0 = 1.0f / l0, i1 = 1.0f / l1;
    const int r0 = q0 + wid * 16 + (lane >> 2);
    #pragma unroll
    for (int nt = 0; nt < 8; nt++) {
        int d = nt * 8 + (lane & 3) * 2;
        split_store(Oh, Ol, (size_t)(b * SEQ + r0) * DM + hh * 64 + d,     o[nt][0] * i0, o[nt][1] * i0);
        split_store(Oh, Ol, (size_t)(b * SEQ + r0 + 8) * DM + hh * 64 + d, o[nt][2] * i1, o[nt][3] * i1);
    }
    #undef A_ISSUE
}

// ---------------- launch ----------------
extern "C" void kernel_launch(void* const* d_in, const int* in_sizes, int n_in,
                              void* d_out, int out_size) {
    const float* x     = (const float*)d_in[0];
    const float* qkv_w = (const float*)d_in[1];
    const float* qkv_b = (const float*)d_in[2];
    const float* out_w = (const float*)d_in[3];
    const float* out_b = (const float*)d_in[4];
    const float* ff1_w = (const float*)d_in[5];
    const float* ff1_b = (const float*)d_in[6];
    const float* ff2_w = (const float*)d_in[7];
    const float* ff2_b = (const float*)d_in[8];
    const float* ln1_g = (const float*)d_in[9];
    const float* ln1_b = (const float*)d_in[10];
    const float* ln2_g = (const float*)d_in[11];
    const float* ln2_b = (const float*)d_in[12];
    float* out = (float*)d_out;

    __nv_bfloat16 *h1h, *h1l, *qkh, *qkl, *cxh, *cxl, *h2h, *h2l, *ffh, *ffl;
    __nv_bfloat16 *wqh, *wql, *woh, *wol, *w1h, *w1l, *w2h, *w2l;
    float* x1;
    cudaGetSymbolAddress((void**)&h1h, g_h1h); cudaGetSymbolAddress((void**)&h1l, g_h1l);
    cudaGetSymbolAddress((void**)&qkh, g_qkh); cudaGetSymbolAddress((void**)&qkl, g_qkl);
    cudaGetSymbolAddress((void**)&cxh, g_cxh); cudaGetSymbolAddress((void**)&cxl, g_cxl);
    cudaGetSymbolAddress((void**)&h2h, g_h2h); cudaGetSymbolAddress((void**)&h2l, g_h2l);
    cudaGetSymbolAddress((void**)&ffh, g_ffh); cudaGetSymbolAddress((void**)&ffl, g_ffl);
    cudaGetSymbolAddress((void**)&wqh, g_wqh); cudaGetSymbolAddress((void**)&wql, g_wql);
    cudaGetSymbolAddress((void**)&woh, g_woh); cudaGetSymbolAddress((void**)&wol, g_wol);
    cudaGetSymbolAddress((void**)&w1h, g_w1h); cudaGetSymbolAddress((void**)&w1l, g_w1l);
    cudaGetSymbolAddress((void**)&w2h, g_w2h); cudaGetSymbolAddress((void**)&w2l, g_w2l);
    cudaGetSymbolAddress((void**)&x1,  g_x1);

    // weight splits (row-major [K][N], B operand staged K-major as in R3)
    wconv<<<(DM * DQKV / 4 + 255) / 256, 256>>>(qkv_w, wqh, wql, DM * DQKV / 4);
    wconv<<<(DM * DM   / 4 + 255) / 256, 256>>>(out_w, woh, wol, DM * DM / 4);
    wconv<<<(DM * DFF  / 4 + 255) / 256, 256>>>(ff1_w, w1h, w1l, DM * DFF / 4);
    wconv<<<(DFF * DM  / 4 + 255) / 256, 256>>>(ff2_w, w2h, w2l, DFF * DM / 4);

    // 1. LN1 -> planes
    ln_kernel<<<TOK, 256>>>(x, ln1_g, ln1_b, h1h, h1l);
    // 2. QKV projection (Q pre-scaled by 0.125) -> planes
    mgemm<0><<<dim3(DQKV / 128, TOK / 128), 256>>>(h1h, h1l, wqh, wql, qkv_b, nullptr,
                                                   nullptr, qkh, qkl, TOK, DQKV, DM);
    // 3. attention -> ctx planes
    attn_kernel<<<dim3(SEQ / 64, 16, 4), 128>>>(qkh, qkl, cxh, cxl);
    // 4. out projection + residual -> x1 (fp32)
    mgemm<1><<<dim3(DM / 128, TOK / 128), 256>>>(cxh, cxl, woh, wol, out_b, x,
                                                 x1, nullptr, nullptr, TOK, DM, DM);
    // 5. LN2 -> planes
    ln_kernel<<<TOK, 256>>>(x1, ln2_g, ln2_b, h2h, h2l);
    // 6. FF1 + exact GELU -> planes
    mgemm<2><<<dim3(DFF / 128, TOK / 128), 256>>>(h2h, h2l, w1h, w1l, ff1_b, nullptr,
                                                  nullptr, ffh, ffl, TOK, DFF, DM);
    // 7. FF2 + residual -> out (fp32)
    mgemm<1><<<dim3(DM / 128, TOK / 128), 256>>>(ffh, ffl, w2h, w2l, ff2_b, x1,
                                                 out, nullptr, nullptr, TOK, DM, DFF);
}

// round 12
// speedup vs baseline: 1.2017x; 1.2017x over previous
#include <cuda_runtime.h>
#include <cuda_bf16.h>
#include <cuda_fp16.h>
#include <stdint.h>
#include <math.h>

#define TOK   8192
#define DM    1024
#define DQKV  3072
#define DFF   2048
#define SEQ   2048

// ---------------- scratch planes (device globals: allocation-free) ----------------
__device__ __nv_bfloat16 g_h1h[TOK*DM],   g_h1l[TOK*DM];     // LN1 out
__device__ __half        g_qk [TOK*DQKV];                    // qkv fp16 (Q pre-scaled)
__device__ __nv_bfloat16 g_cxh[TOK*DM],   g_cxl[TOK*DM];     // attn ctx
__device__ __nv_bfloat16 g_h2h[TOK*DM],   g_h2l[TOK*DM];     // LN2 out
__device__ __nv_bfloat16 g_ffh[TOK*DFF],  g_ffl[TOK*DFF];    // ff1 out (post-GELU)
__device__ float         g_x1 [TOK*DM];                      // residual1 fp32
__device__ __nv_bfloat16 g_wqh[DM*DQKV],  g_wql[DM*DQKV];
__device__ __nv_bfloat16 g_woh[DM*DM],    g_wol[DM*DM];
__device__ __nv_bfloat16 g_w1h[DM*DFF],   g_w1l[DM*DFF];
__device__ __nv_bfloat16 g_w2h[DFF*DM],   g_w2l[DFF*DM];

// ---------------- helpers ----------------
__device__ __forceinline__ unsigned pk2(float lo, float hi) {   // bf16x2, lo -> bits[15:0]
    unsigned d;
    asm("cvt.rn.bf16x2.f32 %0, %1, %2;" : "=r"(d) : "f"(hi), "f"(lo));
    return d;
}
__device__ __forceinline__ unsigned pk2h(float lo, float hi) {  // f16x2, lo -> bits[15:0]
    unsigned d;
    asm("cvt.rn.f16x2.f32 %0, %1, %2;" : "=r"(d) : "f"(hi), "f"(lo));
    return d;
}
__device__ __forceinline__ void split_store(__nv_bfloat16* H, __nv_bfloat16* L,
                                            size_t off, float x0, float x1) {
    float h0 = __bfloat162float(__float2bfloat16(x0));
    float h1 = __bfloat162float(__float2bfloat16(x1));
    *(unsigned*)((char*)H + off*2) = pk2(h0, h1);
    *(unsigned*)((char*)L + off*2) = pk2(x0 - h0, x1 - h1);
}
__device__ __forceinline__ void ldsm4(unsigned& r0, unsigned& r1, unsigned& r2, unsigned& r3, unsigned a) {
    asm volatile("ldmatrix.sync.aligned.m8n8.x4.shared.b16 {%0,%1,%2,%3}, [%4];"
                 : "=r"(r0), "=r"(r1), "=r"(r2), "=r"(r3) : "r"(a));
}
__device__ __forceinline__ void ldsm2(unsigned& r0, unsigned& r1, unsigned a) {
    asm volatile("ldmatrix.sync.aligned.m8n8.x2.shared.b16 {%0,%1}, [%2];"
                 : "=r"(r0), "=r"(r1) : "r"(a));
}
__device__ __forceinline__ void ldsm2t(unsigned& r0, unsigned& r1, unsigned a) {
    asm volatile("ldmatrix.sync.aligned.m8n8.x2.trans.shared.b16 {%0,%1}, [%2];"
                 : "=r"(r0), "=r"(r1) : "r"(a));
}
__device__ __forceinline__ void mma16816(float* c, const unsigned* a, const unsigned* b) {
    asm("mma.sync.aligned.m16n8k16.row.col.f32.bf16.bf16.f32 "
        "{%0,%1,%2,%3},{%4,%5,%6,%7},{%8,%9},{%0,%1,%2,%3};"
        : "+f"(c[0]), "+f"(c[1]), "+f"(c[2]), "+f"(c[3])
        : "r"(a[0]), "r"(a[1]), "r"(a[2]), "r"(a[3]), "r"(b[0]), "r"(b[1]));
}
__device__ __forceinline__ void mma16816h(float* c, const unsigned* a, const unsigned* b) {
    asm("mma.sync.aligned.m16n8k16.row.col.f32.f16.f16.f32 "
        "{%0,%1,%2,%3},{%4,%5,%6,%7},{%8,%9},{%0,%1,%2,%3};"
        : "+f"(c[0]), "+f"(c[1]), "+f"(c[2]), "+f"(c[3])
        : "r"(a[0]), "r"(a[1]), "r"(a[2]), "r"(a[3]), "r"(b[0]), "r"(b[1]));
}
#define CPA(dst, src) asm volatile("cp.async.cg.shared.global [%0], [%1], 16;" ::"r"(dst), "l"(src))
#define CPC()         asm volatile("cp.async.commit_group;")
#define CPW(n)        asm volatile("cp.async.wait_group %0;" ::"n"(n))

// ---------------- weight split ----------------
__global__ void wconv(const float* __restrict__ W, __nv_bfloat16* __restrict__ H,
                      __nv_bfloat16* __restrict__ L, int n4) {
    int i = blockIdx.x * 256 + threadIdx.x;
    if (i >= n4) return;
    float4 v = ((const float4*)W)[i];
    split_store(H, L, (size_t)i * 4,     v.x, v.y);
    split_store(H, L, (size_t)i * 4 + 2, v.z, v.w);
}

// ---------------- LayerNorm -> hi/lo planes ----------------
__global__ void ln_kernel(const float* __restrict__ x, const float* __restrict__ gam,
                          const float* __restrict__ bet,
                          __nv_bfloat16* __restrict__ H, __nv_bfloat16* __restrict__ L) {
    const int row = blockIdx.x;
    const int t   = threadIdx.x;
    const float* xr = x + (size_t)row * DM;
    const int c0 = t * 4;
    float4 v = *(const float4*)(xr + c0);
    float s  = v.x + v.y + v.z + v.w;
    float ss = v.x*v.x + v.y*v.y + v.z*v.z + v.w*v.w;
    #pragma unroll
    for (int o = 16; o; o >>= 1) {
        s  += __shfl_xor_sync(0xffffffffu, s,  o);
        ss += __shfl_xor_sync(0xffffffffu, ss, o);
    }
    __shared__ float sm[8], sm2[8];
    const int w = t >> 5;
    if ((t & 31) == 0) { sm[w] = s; sm2[w] = ss; }
    __syncthreads();
    if (w == 0) {
        float a = (t < 8) ? sm[t] : 0.f;
        float c = (t < 8) ? sm2[t] : 0.f;
        #pragma unroll
        for (int o = 4; o; o >>= 1) {
            a += __shfl_xor_sync(0xffffffffu, a, o);
            c += __shfl_xor_sync(0xffffffffu, c, o);
        }
        if (t == 0) {
            float mu = a * (1.0f / DM);
            float var = c * (1.0f / DM) - mu * mu;
            sm[0] = mu; sm2[0] = rsqrtf(var + 1e-5f);
        }
    }
    __syncthreads();
    const float mu = sm[0], rs = sm2[0];
    float4 g4 = *(const float4*)(gam + c0);
    float4 b4 = *(const float4*)(bet + c0);
    float o0 = (v.x - mu) * rs * g4.x + b4.x;
    float o1 = (v.y - mu) * rs * g4.y + b4.y;
    float o2 = (v.z - mu) * rs * g4.z + b4.z;
    float o3 = (v.w - mu) * rs * g4.w + b4.w;
    size_t off = (size_t)row * DM + c0;
    split_store(H, L, off,     o0, o1);
    split_store(H, L, off + 2, o2, o3);
}

// ---------------- split-bf16 tensor-core GEMM (3-term, as R3/R11) ----------------
// EPI: 0 = bias (+0.125 on cols<1024) -> fp16 single plane (outHalf)
//      1 = bias + residual -> fp32 (outF)
//      2 = bias + exact GELU -> bf16 hi/lo planes (outH/outL)
template<int EPI>
__global__ __launch_bounds__(256, 2)
void mgemm(const __nv_bfloat16* __restrict__ Ah, const __nv_bfloat16* __restrict__ Al,
           const __nv_bfloat16* __restrict__ Bh, const __nv_bfloat16* __restrict__ Bl,
           const float* __restrict__ bias, const float* __restrict__ res,
           float* __restrict__ outF, __nv_bfloat16* __restrict__ outH, __nv_bfloat16* __restrict__ outL,
           __half* __restrict__ outHalf,
           int M, int N, int K) {
    __shared__ char smem[49152];
    const unsigned sbase = (unsigned)__cvta_generic_to_shared(smem);
    const int tid = threadIdx.x;
    const int rb = blockIdx.y << 7, cb = blockIdx.x << 7;

    const __nv_bfloat16* aS[2]; unsigned aD[2];
    const __nv_bfloat16* bS[2]; unsigned bD[2];
    #pragma unroll
    for (int j = 0; j < 2; j++) {
        int ca = tid + j * 256;
        int m = ca & 127, f = ca >> 7;
        int p = f >> 1, kc = f & 1;
        aS[j] = (p ? Al : Ah) + (size_t)(rb + m) * K + kc * 8;
        aD[j] = (m >> 1) * 128 + ((((m & 1) * 4) + p * 2 + kc) ^ ((m >> 1) & 7)) * 16;
        int nc = ca & 15, k = (ca >> 4) & 15, p2 = ca >> 8;
        bS[j] = (p2 ? Bl : Bh) + (size_t)k * N + cb + nc * 8;
        bD[j] = 8192 + p2 * 4096 + k * 256 + ((nc ^ (k & 7)) * 16);
    }
    const int nk = K >> 4;

    #define G_ISSUE(st, i) do { unsigned _b = sbase + (st) * 16384;                      \
        CPA(_b + aD[0], aS[0] + (i) * 16);  CPA(_b + aD[1], aS[1] + (i) * 16);           \
        CPA(_b + bD[0], bS[0] + (size_t)(i) * 16 * N);                                   \
        CPA(_b + bD[1], bS[1] + (size_t)(i) * 16 * N);  CPC(); } while (0)

    G_ISSUE(0, 0);
    G_ISSUE(1, 1);

    const int wid = tid >> 5, lane = tid & 31;
    const int wm = (wid >> 2) * 64, wn = (wid & 3) * 32;
    const int arl = (lane & 7) + 8 * ((lane >> 3) & 1);
    const int akc = (lane >> 4) & 1;
    const int brow = lane & 15;

    float acc[4][4][4];
    #pragma unroll
    for (int a = 0; a < 4; a++)
        #pragma unroll
        for (int b = 0; b < 4; b++)
            #pragma unroll
            for (int e = 0; e < 4; e++) acc[a][b][e] = 0.f;

    for (int i = 0; i < nk; i++) {
        if (i == nk - 1) { CPW(0); } else { CPW(1); }
        __syncthreads();
        if (i + 2 < nk) {
            int st = (i + 2) % 3;
            G_ISSUE(st, i + 2);
        }
        const unsigned stb = sbase + (i % 3) * 16384;

        unsigned bh[4][2], bl[4][2];
        #pragma unroll
        for (int nt = 0; nt < 4; nt++) {
            int nc = (wn + nt * 8) >> 3;
            unsigned ad = stb + 8192 + brow * 256 + ((nc ^ (brow & 7)) * 16);
            ldsm2t(bh[nt][0], bh[nt][1], ad);
            ldsm2t(bl[nt][0], bl[nt][1], ad + 4096);
        }
        #pragma unroll
        for (int mt = 0; mt < 4; mt++) {
            int m = wm + mt * 16 + arl;
            unsigned base = stb + (m >> 1) * 128;
            unsigned Af[4], Lf[4];
            ldsm4(Af[0], Af[1], Af[2], Af[3], base + ((((m & 1) * 4) + akc)     ^ ((m >> 1) & 7)) * 16);
            ldsm4(Lf[0], Lf[1], Lf[2], Lf[3], base + ((((m & 1) * 4) + 2 + akc) ^ ((m >> 1) & 7)) * 16);
            #pragma unroll
            for (int nt = 0; nt < 4; nt++) mma16816(acc[mt][nt], Af, bh[nt]);
            #pragma unroll
            for (int nt = 0; nt < 4; nt++) mma16816(acc[mt][nt], Af, bl[nt]);
            #pragma unroll
            for (int nt = 0; nt < 4; nt++) mma16816(acc[mt][nt], Lf, bh[nt]);
        }
        __syncthreads();
    }

    const float qs = (EPI == 0 && cb < 1024) ? 0.125f : 1.0f;
    #pragma unroll
    for (int mt = 0; mt < 4; mt++) {
        #pragma unroll
        for (int nt = 0; nt < 4; nt++) {
            int gr0 = rb + wm + mt * 16 + (lane >> 2);
            int gc  = cb + wn + nt * 8 + (lane & 3) * 2;
            float b0 = bias[gc], b1 = bias[gc + 1];
            #pragma unroll
            for (int hf = 0; hf < 2; hf++) {
                int gr = gr0 + hf * 8;
                float v0 = acc[mt][nt][hf * 2 + 0] + b0;
                float v1 = acc[mt][nt][hf * 2 + 1] + b1;
                size_t off = (size_t)gr * N + gc;
                if (EPI == 0) {
                    *(unsigned*)((char*)outHalf + off * 2) = pk2h(v0 * qs, v1 * qs);
                } else if (EPI == 1) {
                    v0 += res[off]; v1 += res[off + 1];
                    outF[off] = v0; outF[off + 1] = v1;
                } else {
                    v0 = 0.5f * v0 * (1.0f + erff(v0 * 0.70710678118654752f));
                    v1 = 0.5f * v1 * (1.0f + erff(v1 * 0.70710678118654752f));
                    split_store(outH, outL, off, v0, v1);
                }
            }
        }
    }
    #undef G_ISSUE
}

// ---------------- fp16 single-term flash attention ----------------
// block = 128 thr (4 warps), 64 queries; 64-key tiles, double-buffered.
// smem: Q [0,8K): row*128B (64 d fp16, swizzled 16B chunks);
//       KV stage s at 8K+s*16K: K +0 (8KB), V +8K (8KB).
__global__ __launch_bounds__(128, 3)
void attn_kernel(const __half* __restrict__ P, __nv_bfloat16* __restrict__ Oh,
                 __nv_bfloat16* __restrict__ Ol) {
    __shared__ char smem[40960];
    const unsigned sbase = (unsigned)__cvta_generic_to_shared(smem);
    const int b = blockIdx.z, hh = blockIdx.y, q0 = blockIdx.x * 64;
    const int tid = threadIdx.x, wid = tid >> 5, lane = tid & 31;

    // ---- stage Q (64 rows x 8 chunks of 16B) ----
    #pragma unroll
    for (int j = 0; j < 4; j++) {
        int qc = tid + j * 128;
        int row = qc & 63, dc = qc >> 6;
        const __half* src = P + (size_t)(b * SEQ + q0 + row) * DQKV + hh * 64 + dc * 8;
        *(uint4*)(smem + row * 128 + ((dc ^ (row & 7)) * 16)) = *(const uint4*)src;
    }
    __syncthreads();

    const int arl = (lane & 7) + 8 * ((lane >> 3) & 1);
    const int akc = (lane >> 4) & 1;
    unsigned qf[4][4];
    #pragma unroll
    for (int kc = 0; kc < 4; kc++) {
        int row = wid * 16 + arl;
        int dc = kc * 2 + akc;
        unsigned ad = sbase + row * 128 + ((dc ^ (row & 7)) * 16);
        ldsm4(qf[kc][0], qf[kc][1], qf[kc][2], qf[kc][3], ad);
    }
    __syncthreads();

    // ---- KV staging: 8 chunks/thread/stage (K 512 + V 512 chunks) ----
    const __half* kvS[8]; unsigned kvD[8];
    #pragma unroll
    for (int j = 0; j < 8; j++) {
        int cc = tid + j * 128;
        int dc = cc & 7, key = (cc >> 3) & 63, mat = cc >> 9;   // mat: 0=K,1=V
        kvS[j] = P + (size_t)(b * SEQ + key) * DQKV + 1024 + mat * 1024 + hh * 64 + dc * 8;
        kvD[j] = 8192 + mat * 8192 + key * 128 + ((dc ^ (key & 7)) * 16);
    }
    #define A_ISSUE(t) do { unsigned _b = sbase + ((t) & 1) * 16384;                     \
        _Pragma("unroll") for (int j = 0; j < 8; j++)                                    \
            CPA(_b + kvD[j], kvS[j] + (size_t)(t) * 64 * DQKV);                          \
        CPC(); } while (0)

    A_ISSUE(0);

    float o[8][4];
    #pragma unroll
    for (int i = 0; i < 8; i++)
        #pragma unroll
        for (int e = 0; e < 4; e++) o[i][e] = 0.f;
    float m0 = -1e30f, m1 = -1e30f, l0 = 0.f, l1 = 0.f;

    for (int t = 0; t < SEQ / 64; t++) {
        if (t + 1 < SEQ / 64) { A_ISSUE(t + 1); CPW(1); } else { CPW(0); }
        __syncthreads();
        const unsigned stb = sbase + (t & 1) * 16384;

        // S = Q K^T  (16x64 per warp), single fp16 term
        float s[8][4];
        #pragma unroll
        for (int nt = 0; nt < 8; nt++)
            #pragma unroll
            for (int e = 0; e < 4; e++) s[nt][e] = 0.f;
        {
            int row = (lane & 7);
            int kch = ((lane >> 3) & 1);
            #pragma unroll
            for (int kc = 0; kc < 4; kc++) {
                int chunk = kc * 2 + kch;
                #pragma unroll
                for (int nt = 0; nt < 8; nt++) {
                    int r = nt * 8 + row;
                    unsigned kd = stb + 8192 + r * 128 + ((chunk ^ (r & 7)) * 16);
                    unsigned kh[2];
                    ldsm2(kh[0], kh[1], kd);
                    mma16816h(s[nt], qf[kc], kh);
                }
            }
        }
        // online softmax (rows: lo = lane/4, hi = lane/4+8)
        float mx0 = -1e30f, mx1 = -1e30f;
        #pragma unroll
        for (int nt = 0; nt < 8; nt++) {
            mx0 = fmaxf(mx0, fmaxf(s[nt][0], s[nt][1]));
            mx1 = fmaxf(mx1, fmaxf(s[nt][2], s[nt][3]));
        }
        mx0 = fmaxf(mx0, __shfl_xor_sync(0xffffffffu, mx0, 1));
        mx0 = fmaxf(mx0, __shfl_xor_sync(0xffffffffu, mx0, 2));
        mx1 = fmaxf(mx1, __shfl_xor_sync(0xffffffffu, mx1, 1));
        mx1 = fmaxf(mx1, __shfl_xor_sync(0xffffffffu, mx1, 2));
        float mn0 = fmaxf(m0, mx0), mn1 = fmaxf(m1, mx1);
        float c0 = __expf(m0 - mn0), c1 = __expf(m1 - mn1);
        m0 = mn0; m1 = mn1;
        l0 *= c0; l1 *= c1;
        #pragma unroll
        for (int nt = 0; nt < 8; nt++) {
            s[nt][0] = __expf(s[nt][0] - m0); l0 += s[nt][0];
            s[nt][1] = __expf(s[nt][1] - m0); l0 += s[nt][1];
            s[nt][2] = __expf(s[nt][2] - m1); l1 += s[nt][2];
            s[nt][3] = __expf(s[nt][3] - m1); l1 += s[nt][3];
        }
        #pragma unroll
        for (int nt = 0; nt < 8; nt++) {
            o[nt][0] *= c0; o[nt][1] *= c0; o[nt][2] *= c1; o[nt][3] *= c1;
        }
        // P fragments (fp16, C->A layout identity); kc2 covers 16 keys each
        unsigned ph[4][4];
        #pragma unroll
        for (int kc2 = 0; kc2 < 4; kc2++) {
            ph[kc2][0] = pk2h(s[2 * kc2][0],     s[2 * kc2][1]);
            ph[kc2][1] = pk2h(s[2 * kc2][2],     s[2 * kc2][3]);
            ph[kc2][2] = pk2h(s[2 * kc2 + 1][0], s[2 * kc2 + 1][1]);
            ph[kc2][3] = pk2h(s[2 * kc2 + 1][2], s[2 * kc2 + 1][3]);
        }
        // O += P V, single fp16 term
        #pragma unroll
        for (int kc2 = 0; kc2 < 4; kc2++) {
            int row = kc2 * 16 + (lane & 15);
            #pragma unroll
            for (int nt = 0; nt < 8; nt++) {
                unsigned vd = stb + 16384 + row * 128 + ((nt ^ (row & 7)) * 16);
                unsigned vh[2];
                ldsm2t(vh[0], vh[1], vd);
                mma16816h(o[nt], ph[kc2], vh);
            }
        }
        __syncthreads();
    }

    l0 += __shfl_xor_sync(0xffffffffu, l0, 1);
    l0 += __shfl_xor_sync(0xffffffffu, l0, 2);
    l1 += __shfl_xor_sync(0xffffffffu, l1, 1);
    l1 += __shfl_xor_sync(0xffffffffu, l1, 2);
    const float i0 = 1.0f / l0, i1 = 1.0f / l1;
    const int r0 = q0 + wid * 16 + (lane >> 2);
    #pragma unroll
    for (int nt = 0; nt < 8; nt++) {
        int d = nt * 8 + (lane & 3) * 2;
        split_store(Oh, Ol, (size_t)(b * SEQ + r0) * DM + hh * 64 + d,     o[nt][0] * i0, o[nt][1] * i0);
        split_store(Oh, Ol, (size_t)(b * SEQ + r0 + 8) * DM + hh * 64 + d, o[nt][2] * i1, o[nt][3] * i1);
    }
    #undef A_ISSUE
}

// ---------------- launch ----------------
extern "C" void kernel_launch(void* const* d_in, const int* in_sizes, int n_in,
                              void* d_out, int out_size) {
    const float* x     = (const float*)d_in[0];
    const float* qkv_w = (const float*)d_in[1];
    const float* qkv_b = (const float*)d_in[2];
    const float* out_w = (const float*)d_in[3];
    const float* out_b = (const float*)d_in[4];
    const float* ff1_w = (const float*)d_in[5];
    const float* ff1_b = (const float*)d_in[6];
    const float* ff2_w = (const float*)d_in[7];
    const float* ff2_b = (const float*)d_in[8];
    const float* ln1_g = (const float*)d_in[9];
    const float* ln1_b = (const float*)d_in[10];
    const float* ln2_g = (const float*)d_in[11];
    const float* ln2_b = (const float*)d_in[12];
    float* out = (float*)d_out;

    __nv_bfloat16 *h1h, *h1l, *cxh, *cxl, *h2h, *h2l, *ffh, *ffl;
    __nv_bfloat16 *wqh, *wql, *woh, *wol, *w1h, *w1l, *w2h, *w2l;
    __half* qk;
    float* x1;
    cudaGetSymbolAddress((void**)&h1h, g_h1h); cudaGetSymbolAddress((void**)&h1l, g_h1l);
    cudaGetSymbolAddress((void**)&qk,  g_qk);
    cudaGetSymbolAddress((void**)&cxh, g_cxh); cudaGetSymbolAddress((void**)&cxl, g_cxl);
    cudaGetSymbolAddress((void**)&h2h, g_h2h); cudaGetSymbolAddress((void**)&h2l, g_h2l);
    cudaGetSymbolAddress((void**)&ffh, g_ffh); cudaGetSymbolAddress((void**)&ffl, g_ffl);
    cudaGetSymbolAddress((void**)&wqh, g_wqh); cudaGetSymbolAddress((void**)&wql, g_wql);
    cudaGetSymbolAddress((void**)&woh, g_woh); cudaGetSymbolAddress((void**)&wol, g_wol);
    cudaGetSymbolAddress((void**)&w1h, g_w1h); cudaGetSymbolAddress((void**)&w1l, g_w1l);
    cudaGetSymbolAddress((void**)&w2h, g_w2h); cudaGetSymbolAddress((void**)&w2l, g_w2l);
    cudaGetSymbolAddress((void**)&x1,  g_x1);

    // weight splits
    wconv<<<(DM * DQKV / 4 + 255) / 256, 256>>>(qkv_w, wqh, wql, DM * DQKV / 4);
    wconv<<<(DM * DM   / 4 + 255) / 256, 256>>>(out_w, woh, wol, DM * DM / 4);
    wconv<<<(DM * DFF  / 4 + 255) / 256, 256>>>(ff1_w, w1h, w1l, DM * DFF / 4);
    wconv<<<(DFF * DM  / 4 + 255) / 256, 256>>>(ff2_w, w2h, w2l, DFF * DM / 4);

    // 1. LN1 -> planes
    ln_kernel<<<TOK, 256>>>(x, ln1_g, ln1_b, h1h, h1l);
    // 2. QKV projection (Q pre-scaled by 0.125) -> fp16 plane
    mgemm<0><<<dim3(DQKV / 128, TOK / 128), 256>>>(h1h, h1l, wqh, wql, qkv_b, nullptr,
                                                   nullptr, nullptr, nullptr, qk, TOK, DQKV, DM);
    // 3. attention (fp16 single-term) -> ctx bf16 planes
    attn_kernel<<<dim3(SEQ / 64, 16, 4), 128>>>(qk, cxh, cxl);
    // 4. out projection + residual -> x1 (fp32)
    mgemm<1><<<dim3(DM / 128, TOK / 128), 256>>>(cxh, cxl, woh, wol, out_b, x,
                                                 x1, nullptr, nullptr, nullptr, TOK, DM, DM);
    // 5. LN2 -> planes
    ln_kernel<<<TOK, 256>>>(x1, ln2_g, ln2_b, h2h, h2l);
    // 6. FF1 + exact GELU -> planes
    mgemm<2><<<dim3(DFF / 128, TOK / 128), 256>>>(h2h, h2l, w1h, w1l, ff1_b, nullptr,
                                                  nullptr, ffh, ffl, nullptr, TOK, DFF, DM);
    // 7. FF2 + residual -> out (fp32)
    mgemm<1><<<dim3(DM / 128, TOK / 128), 256>>>(ffh, ffl, w2h, w2l, ff2_b, x1,
                                                 out, nullptr, nullptr, nullptr, TOK, DM, DFF);
}

// round 17
// speedup vs baseline: 1.9052x; 1.5855x over previous
#include <cuda_runtime.h>
#include <cuda_bf16.h>
#include <cuda_fp16.h>
#include <stdint.h>
#include <math.h>

#define TOK   8192
#define DM    1024
#define DQKV  3072
#define DFF   2048
#define SEQ   2048

// ---------------- scratch planes (device globals: allocation-free) ----------------
__device__ __half g_h1[TOK*DM];        // LN1 out (fp16)
__device__ __half g_qk[TOK*DQKV];      // qkv fp16 (Q pre-scaled)
__device__ __half g_cx[TOK*DM];        // attn ctx (fp16)
__device__ __half g_h2[TOK*DM];        // LN2 out (fp16)
__device__ __half g_ff[TOK*DFF];       // ff1 out post-GELU (fp16)
__device__ float  g_x1[TOK*DM];        // residual1 fp32
// weights: fp16 hi/lo planes, row-major [K][N]
__device__ __half g_wqh[DM*DQKV],  g_wql[DM*DQKV];
__device__ __half g_woh[DM*DM],    g_wol[DM*DM];
__device__ __half g_w1h[DM*DFF],   g_w1l[DM*DFF];
__device__ __half g_w2h[DFF*DM],   g_w2l[DFF*DM];

// ---------------- helpers ----------------
__device__ __forceinline__ unsigned pk2h(float lo, float hi) {  // f16x2, lo -> bits[15:0]
    unsigned d;
    asm("cvt.rn.f16x2.f32 %0, %1, %2;" : "=r"(d) : "f"(hi), "f"(lo));
    return d;
}
__device__ __forceinline__ void ldsm4(unsigned& r0, unsigned& r1, unsigned& r2, unsigned& r3, unsigned a) {
    asm volatile("ldmatrix.sync.aligned.m8n8.x4.shared.b16 {%0,%1,%2,%3}, [%4];"
                 : "=r"(r0), "=r"(r1), "=r"(r2), "=r"(r3) : "r"(a));
}
__device__ __forceinline__ void ldsm2(unsigned& r0, unsigned& r1, unsigned a) {
    asm volatile("ldmatrix.sync.aligned.m8n8.x2.shared.b16 {%0,%1}, [%2];"
                 : "=r"(r0), "=r"(r1) : "r"(a));
}
__device__ __forceinline__ void ldsm2t(unsigned& r0, unsigned& r1, unsigned a) {
    asm volatile("ldmatrix.sync.aligned.m8n8.x2.trans.shared.b16 {%0,%1}, [%2];"
                 : "=r"(r0), "=r"(r1) : "r"(a));
}
__device__ __forceinline__ void mma16816h(float* c, const unsigned* a, const unsigned* b) {
    asm("mma.sync.aligned.m16n8k16.row.col.f32.f16.f16.f32 "
        "{%0,%1,%2,%3},{%4,%5,%6,%7},{%8,%9},{%0,%1,%2,%3};"
        : "+f"(c[0]), "+f"(c[1]), "+f"(c[2]), "+f"(c[3])
        : "r"(a[0]), "r"(a[1]), "r"(a[2]), "r"(a[3]), "r"(b[0]), "r"(b[1]));
}
#define CPA(dst, src) asm volatile("cp.async.cg.shared.global [%0], [%1], 16;" ::"r"(dst), "l"(src))
#define CPC()         asm volatile("cp.async.commit_group;")
#define CPW(n)        asm volatile("cp.async.wait_group %0;" ::"n"(n))

// ---------------- weight split: W fp32 -> fp16 hi/lo planes ----------------
__global__ void wconv(const float* __restrict__ W, __half* __restrict__ H,
                      __half* __restrict__ L, int n4) {
    int i = blockIdx.x * 256 + threadIdx.x;
    if (i >= n4) return;
    float4 v = ((const float4*)W)[i];
    __half h0 = __float2half(v.x), h1 = __float2half(v.y);
    __half h2 = __float2half(v.z), h3 = __float2half(v.w);
    uint2 hw, lw;
    hw.x = ((unsigned)__half_as_ushort(h1) << 16) | __half_as_ushort(h0);
    hw.y = ((unsigned)__half_as_ushort(h3) << 16) | __half_as_ushort(h2);
    lw.x = pk2h(v.x - __half2float(h0), v.y - __half2float(h1));
    lw.y = pk2h(v.z - __half2float(h2), v.w - __half2float(h3));
    *(uint2*)(H + (size_t)i * 4) = hw;
    *(uint2*)(L + (size_t)i * 4) = lw;
}

// ---------------- LayerNorm -> single fp16 plane ----------------
__global__ void ln_kernel(const float* __restrict__ x, const float* __restrict__ gam,
                          const float* __restrict__ bet, __half* __restrict__ H) {
    const int row = blockIdx.x;
    const int t   = threadIdx.x;
    const float* xr = x + (size_t)row * DM;
    const int c0 = t * 4;
    float4 v = *(const float4*)(xr + c0);
    float s  = v.x + v.y + v.z + v.w;
    float ss = v.x*v.x + v.y*v.y + v.z*v.z + v.w*v.w;
    #pragma unroll
    for (int o = 16; o; o >>= 1) {
        s  += __shfl_xor_sync(0xffffffffu, s,  o);
        ss += __shfl_xor_sync(0xffffffffu, ss, o);
    }
    __shared__ float sm[8], sm2[8];
    const int w = t >> 5;
    if ((t & 31) == 0) { sm[w] = s; sm2[w] = ss; }
    __syncthreads();
    if (w == 0) {
        float a = (t < 8) ? sm[t] : 0.f;
        float c = (t < 8) ? sm2[t] : 0.f;
        #pragma unroll
        for (int o = 4; o; o >>= 1) {
            a += __shfl_xor_sync(0xffffffffu, a, o);
            c += __shfl_xor_sync(0xffffffffu, c, o);
        }
        if (t == 0) {
            float mu = a * (1.0f / DM);
            float var = c * (1.0f / DM) - mu * mu;
            sm[0] = mu; sm2[0] = rsqrtf(var + 1e-5f);
        }
    }
    __syncthreads();
    const float mu = sm[0], rs = sm2[0];
    float4 g4 = *(const float4*)(gam + c0);
    float4 b4 = *(const float4*)(bet + c0);
    uint2 ow;
    ow.x = pk2h((v.x - mu) * rs * g4.x + b4.x, (v.y - mu) * rs * g4.y + b4.y);
    ow.y = pk2h((v.z - mu) * rs * g4.z + b4.z, (v.w - mu) * rs * g4.w + b4.w);
    *(uint2*)(H + (size_t)row * DM + c0) = ow;
}

// ---------------- 2-term fp16 tensor-core GEMM ----------------
// C[M,N] = A[M,K] @ (Wh+Wl)[K,N] + bias.  A single fp16 plane, W fp16 hi/lo.
// 128x128 block, BK=16, 3-stage cp.async (12KB/stage). 8 warps = 2(m) x 4(n).
// stage layout: A[0,4K): line (r>>2)*128B, chunk ((r&3)*2+c)^((r>>2)&7);
//               Bh[4K,8K), Bl[8K,12K): k row * 256B, chunk nc^(k&7).
// EPI: 0 = bias (+0.125 on cols<1024) -> fp16; 1 = bias+res -> fp32; 2 = bias+GELU -> fp16
template<int EPI>
__global__ __launch_bounds__(256, 2)
void mgemm(const __half* __restrict__ A,
           const __half* __restrict__ Bh, const __half* __restrict__ Bl,
           const float* __restrict__ bias, const float* __restrict__ res,
           float* __restrict__ outF, __half* __restrict__ outHalf,
           int M, int N, int K) {
    __shared__ char smem[36864];
    const unsigned sbase = (unsigned)__cvta_generic_to_shared(smem);
    const int tid = threadIdx.x;
    const int rb = blockIdx.y << 7, cb = blockIdx.x << 7;

    // staging: 3 chunks per thread per stage (1 A, 1 Bh, 1 Bl)
    const int ar = tid >> 1, ac = tid & 1;
    const __half* aS = A + (size_t)(rb + ar) * K + ac * 8;
    const unsigned aD = (ar >> 2) * 128 + ((((ar & 3) * 2 + ac) ^ ((ar >> 2) & 7)) * 16);
    const int bk = tid >> 4, bn = tid & 15;
    const __half* bSh = Bh + (size_t)bk * N + cb + bn * 8;
    const __half* bSl = Bl + (size_t)bk * N + cb + bn * 8;
    const unsigned bD = 4096 + bk * 256 + ((bn ^ (bk & 7)) * 16);
    const int nk = K >> 4;

    #define G_ISSUE(st, i) do { unsigned _b = sbase + (st) * 12288;                      \
        CPA(_b + aD, aS + (i) * 16);                                                     \
        CPA(_b + bD,        bSh + (size_t)(i) * 16 * N);                                 \
        CPA(_b + bD + 4096, bSl + (size_t)(i) * 16 * N);  CPC(); } while (0)

    G_ISSUE(0, 0);
    G_ISSUE(1, 1);

    const int wid = tid >> 5, lane = tid & 31;
    const int wm = (wid >> 2) * 64, wn = (wid & 3) * 32;
    const int arl = (lane & 7) + 8 * ((lane >> 3) & 1);
    const int akc = (lane >> 4) & 1;
    const int brow = lane & 15;

    float acc[4][4][4];
    #pragma unroll
    for (int a = 0; a < 4; a++)
        #pragma unroll
        for (int b = 0; b < 4; b++)
            #pragma unroll
            for (int e = 0; e < 4; e++) acc[a][b][e] = 0.f;

    for (int i = 0; i < nk; i++) {
        if (i == nk - 1) { CPW(0); } else { CPW(1); }
        __syncthreads();
        if (i + 2 < nk) {
            int st = (i + 2) % 3;
            G_ISSUE(st, i + 2);
        }
        const unsigned stb = sbase + (i % 3) * 12288;

        unsigned bh[4][2], bl[4][2];
        #pragma unroll
        for (int nt = 0; nt < 4; nt++) {
            int nc = (wn + nt * 8) >> 3;
            unsigned ad = stb + 4096 + brow * 256 + ((nc ^ (brow & 7)) * 16);
            ldsm2t(bh[nt][0], bh[nt][1], ad);
            ldsm2t(bl[nt][0], bl[nt][1], ad + 4096);
        }
        #pragma unroll
        for (int mt = 0; mt < 4; mt++) {
            int m = wm + mt * 16 + arl;
            unsigned Af[4];
            ldsm4(Af[0], Af[1], Af[2], Af[3],
                  stb + (m >> 2) * 128 + ((((m & 3) * 2 + akc) ^ ((m >> 2) & 7)) * 16));
            #pragma unroll
            for (int nt = 0; nt < 4; nt++) mma16816h(acc[mt][nt], Af, bh[nt]);
            #pragma unroll
            for (int nt = 0; nt < 4; nt++) mma16816h(acc[mt][nt], Af, bl[nt]);
        }
        __syncthreads();
    }

    const float qs = (EPI == 0 && cb < 1024) ? 0.125f : 1.0f;
    #pragma unroll
    for (int mt = 0; mt < 4; mt++) {
        #pragma unroll
        for (int nt = 0; nt < 4; nt++) {
            int gr0 = rb + wm + mt * 16 + (lane >> 2);
            int gc  = cb + wn + nt * 8 + (lane & 3) * 2;
            float b0 = bias[gc], b1 = bias[gc + 1];
            #pragma unroll
            for (int hf = 0; hf < 2; hf++) {
                int gr = gr0 + hf * 8;
                float v0 = acc[mt][nt][hf * 2 + 0] + b0;
                float v1 = acc[mt][nt][hf * 2 + 1] + b1;
                size_t off = (size_t)gr * N + gc;
                if (EPI == 0) {
                    *(unsigned*)((char*)outHalf + off * 2) = pk2h(v0 * qs, v1 * qs);
                } else if (EPI == 1) {
                    outF[off]     = v0 + res[off];
                    outF[off + 1] = v1 + res[off + 1];
                } else {
                    v0 = 0.5f * v0 * (1.0f + erff(v0 * 0.70710678118654752f));
                    v1 = 0.5f * v1 * (1.0f + erff(v1 * 0.70710678118654752f));
                    *(unsigned*)((char*)outHalf + off * 2) = pk2h(v0, v1);
                }
            }
        }
    }
    #undef G_ISSUE
}

// ---------------- fp16 single-term flash attention (as R12; fp16 out) ----------------
__global__ __launch_bounds__(128, 3)
void attn_kernel(const __half* __restrict__ P, __half* __restrict__ O) {
    __shared__ char smem[40960];
    const unsigned sbase = (unsigned)__cvta_generic_to_shared(smem);
    const int b = blockIdx.z, hh = blockIdx.y, q0 = blockIdx.x * 64;
    const int tid = threadIdx.x, wid = tid >> 5, lane = tid & 31;

    #pragma unroll
    for (int j = 0; j < 4; j++) {
        int qc = tid + j * 128;
        int row = qc & 63, dc = qc >> 6;
        const __half* src = P + (size_t)(b * SEQ + q0 + row) * DQKV + hh * 64 + dc * 8;
        *(uint4*)(smem + row * 128 + ((dc ^ (row & 7)) * 16)) = *(const uint4*)src;
    }
    __syncthreads();

    const int arl = (lane & 7) + 8 * ((lane >> 3) & 1);
    const int akc = (lane >> 4) & 1;
    unsigned qf[4][4];
    #pragma unroll
    for (int kc = 0; kc < 4; kc++) {
        int row = wid * 16 + arl;
        int dc = kc * 2 + akc;
        unsigned ad = sbase + row * 128 + ((dc ^ (row & 7)) * 16);
        ldsm4(qf[kc][0], qf[kc][1], qf[kc][2], qf[kc][3], ad);
    }
    __syncthreads();

    const __half* kvS[8]; unsigned kvD[8];
    #pragma unroll
    for (int j = 0; j < 8; j++) {
        int cc = tid + j * 128;
        int dc = cc & 7, key = (cc >> 3) & 63, mat = cc >> 9;
        kvS[j] = P + (size_t)(b * SEQ + key) * DQKV + 1024 + mat * 1024 + hh * 64 + dc * 8;
        kvD[j] = 8192 + mat * 8192 + key * 128 + ((dc ^ (key & 7)) * 16);
    }
    #define A_ISSUE(t) do { unsigned _b = sbase + ((t) & 1) * 16384;                     \
        _Pragma("unroll") for (int j = 0; j < 8; j++)                                    \
            CPA(_b + kvD[j], kvS[j] + (size_t)(t) * 64 * DQKV);                          \
        CPC(); } while (0)

    A_ISSUE(0);

    float o[8][4];
    #pragma unroll
    for (int i = 0; i < 8; i++)
        #pragma unroll
        for (int e = 0; e < 4; e++) o[i][e] = 0.f;
    float m0 = -1e30f, m1 = -1e30f, l0 = 0.f, l1 = 0.f;

    for (int t = 0; t < SEQ / 64; t++) {
        if (t + 1 < SEQ / 64) { A_ISSUE(t + 1); CPW(1); } else { CPW(0); }
        __syncthreads();
        const unsigned stb = sbase + (t & 1) * 16384;

        float s[8][4];
        #pragma unroll
        for (int nt = 0; nt < 8; nt++)
            #pragma unroll
            for (int e = 0; e < 4; e++) s[nt][e] = 0.f;
        {
            int row = (lane & 7);
            int kch = ((lane >> 3) & 1);
            #pragma unroll
            for (int kc = 0; kc < 4; kc++) {
                int chunk = kc * 2 + kch;
                #pragma unroll
                for (int nt = 0; nt < 8; nt++) {
                    int r = nt * 8 + row;
                    unsigned kd = stb + 8192 + r * 128 + ((chunk ^ (r & 7)) * 16);
                    unsigned kh[2];
                    ldsm2(kh[0], kh[1], kd);
                    mma16816h(s[nt], qf[kc], kh);
                }
            }
        }
        float mx0 = -1e30f, mx1 = -1e30f;
        #pragma unroll
        for (int nt = 0; nt < 8; nt++) {
            mx0 = fmaxf(mx0, fmaxf(s[nt][0], s[nt][1]));
            mx1 = fmaxf(mx1, fmaxf(s[nt][2], s[nt][3]));
        }
        mx0 = fmaxf(mx0, __shfl_xor_sync(0xffffffffu, mx0, 1));
        mx0 = fmaxf(mx0, __shfl_xor_sync(0xffffffffu, mx0, 2));
        mx1 = fmaxf(mx1, __shfl_xor_sync(0xffffffffu, mx1, 1));
        mx1 = fmaxf(mx1, __shfl_xor_sync(0xffffffffu, mx1, 2));
        float mn0 = fmaxf(m0, mx0), mn1 = fmaxf(m1, mx1);
        float c0 = __expf(m0 - mn0), c1 = __expf(m1 - mn1);
        m0 = mn0; m1 = mn1;
        l0 *= c0; l1 *= c1;
        #pragma unroll
        for (int nt = 0; nt < 8; nt++) {
            s[nt][0] = __expf(s[nt][0] - m0); l0 += s[nt][0];
            s[nt][1] = __expf(s[nt][1] - m0); l0 += s[nt][1];
            s[nt][2] = __expf(s[nt][2] - m1); l1 += s[nt][2];
            s[nt][3] = __expf(s[nt][3] - m1); l1 += s[nt][3];
        }
        #pragma unroll
        for (int nt = 0; nt < 8; nt++) {
            o[nt][0] *= c0; o[nt][1] *= c0; o[nt][2] *= c1; o[nt][3] *= c1;
        }
        unsigned ph[4][4];
        #pragma unroll
        for (int kc2 = 0; kc2 < 4; kc2++) {
            ph[kc2][0] = pk2h(s[2 * kc2][0],     s[2 * kc2][1]);
            ph[kc2][1] = pk2h(s[2 * kc2][2],     s[2 * kc2][3]);
            ph[kc2][2] = pk2h(s[2 * kc2 + 1][0], s[2 * kc2 + 1][1]);
            ph[kc2][3] = pk2h(s[2 * kc2 + 1][2], s[2 * kc2 + 1][3]);
        }
        #pragma unroll
        for (int kc2 = 0; kc2 < 4; kc2++) {
            int row = kc2 * 16 + (lane & 15);
            #pragma unroll
            for (int nt = 0; nt < 8; nt++) {
                unsigned vd = stb + 16384 + row * 128 + ((nt ^ (row & 7)) * 16);
                unsigned vh[2];
                ldsm2t(vh[0], vh[1], vd);
                mma16816h(o[nt], ph[kc2], vh);
            }
        }
        __syncthreads();
    }

    l0 += __shfl_xor_sync(0xffffffffu, l0, 1);
    l0 += __shfl_xor_sync(0xffffffffu, l0, 2);
    l1 += __shfl_xor_sync(0xffffffffu, l1, 1);
    l1 += __shfl_xor_sync(0xffffffffu, l1, 2);
    const float i0 = 1.0f / l0, i1 = 1.0f / l1;
    const int r0 = q0 + wid * 16 + (lane >> 2);
    #pragma unroll
    for (int nt = 0; nt < 8; nt++) {
        int d = nt * 8 + (lane & 3) * 2;
        size_t off0 = (size_t)(b * SEQ + r0) * DM + hh * 64 + d;
        size_t off1 = (size_t)(b * SEQ + r0 + 8) * DM + hh * 64 + d;
        *(unsigned*)((char*)O + off0 * 2) = pk2h(o[nt][0] * i0, o[nt][1] * i0);
        *(unsigned*)((char*)O + off1 * 2) = pk2h(o[nt][2] * i1, o[nt][3] * i1);
    }
    #undef A_ISSUE
}

// ---------------- launch ----------------
extern "C" void kernel_launch(void* const* d_in, const int* in_sizes, int n_in,
                              void* d_out, int out_size) {
    const float* x     = (const float*)d_in[0];
    const float* qkv_w = (const float*)d_in[1];
    const float* qkv_b = (const float*)d_in[2];
    const float* out_w = (const float*)d_in[3];
    const float* out_b = (const float*)d_in[4];
    const float* ff1_w = (const float*)d_in[5];
    const float* ff1_b = (const float*)d_in[6];
    const float* ff2_w = (const float*)d_in[7];
    const float* ff2_b = (const float*)d_in[8];
    const float* ln1_g = (const float*)d_in[9];
    const float* ln1_b = (const float*)d_in[10];
    const float* ln2_g = (const float*)d_in[11];
    const float* ln2_b = (const float*)d_in[12];
    float* out = (float*)d_out;

    __half *h1, *qk, *cx, *h2, *ff;
    __half *wqh, *wql, *woh, *wol, *w1h, *w1l, *w2h, *w2l;
    float* x1;
    cudaGetSymbolAddress((void**)&h1, g_h1);
    cudaGetSymbolAddress((void**)&qk, g_qk);
    cudaGetSymbolAddress((void**)&cx, g_cx);
    cudaGetSymbolAddress((void**)&h2, g_h2);
    cudaGetSymbolAddress((void**)&ff, g_ff);
    cudaGetSymbolAddress((void**)&wqh, g_wqh); cudaGetSymbolAddress((void**)&wql, g_wql);
    cudaGetSymbolAddress((void**)&woh, g_woh); cudaGetSymbolAddress((void**)&wol, g_wol);
    cudaGetSymbolAddress((void**)&w1h, g_w1h); cudaGetSymbolAddress((void**)&w1l, g_w1l);
    cudaGetSymbolAddress((void**)&w2h, g_w2h); cudaGetSymbolAddress((void**)&w2l, g_w2l);
    cudaGetSymbolAddress((void**)&x1,  g_x1);

    // weight splits (fp16 hi/lo)
    wconv<<<(DM * DQKV / 4 + 255) / 256, 256>>>(qkv_w, wqh, wql, DM * DQKV / 4);
    wconv<<<(DM * DM   / 4 + 255) / 256, 256>>>(out_w, woh, wol, DM * DM / 4);
    wconv<<<(DM * DFF  / 4 + 255) / 256, 256>>>(ff1_w, w1h, w1l, DM * DFF / 4);
    wconv<<<(DFF * DM  / 4 + 255) / 256, 256>>>(ff2_w, w2h, w2l, DFF * DM / 4);

    // 1. LN1 -> fp16
    ln_kernel<<<TOK, 256>>>(x, ln1_g, ln1_b, h1);
    // 2. QKV projection (Q pre-scaled by 0.125) -> fp16
    mgemm<0><<<dim3(DQKV / 128, TOK / 128), 256>>>(h1, wqh, wql, qkv_b, nullptr,
                                                   nullptr, qk, TOK, DQKV, DM);
    // 3. attention (fp16 single-term) -> fp16 ctx
    attn_kernel<<<dim3(SEQ / 64, 16, 4), 128>>>(qk, cx);
    // 4. out projection + residual -> x1 (fp32)
    mgemm<1><<<dim3(DM / 128, TOK / 128), 256>>>(cx, woh, wol, out_b, x,
                                                 x1, nullptr, TOK, DM, DM);
    // 5. LN2 -> fp16
    ln_kernel<<<TOK, 256>>>(x1, ln2_g, ln2_b, h2);
    // 6. FF1 + exact GELU -> fp16
    mgemm<2><<<dim3(DFF / 128, TOK / 128), 256>>>(h2, w1h, w1l, ff1_b, nullptr,
                                                  nullptr, ff, TOK, DFF, DM);
    // 7. FF2 + residual -> out (fp32)
    mgemm<1><<<dim3(DM / 128, TOK / 128), 256>>>(ff, w2h, w2l, ff2_b, x1,
                                                 out, nullptr, TOK, DM, DFF);
}